// round 4
// baseline (speedup 1.0000x reference)
#include <cuda_runtime.h>
#include <math.h>

#define NG   8192
#define SS   64
#define DD   128
#define HH   256
#define KK   8
#define GPB  8
#define EPSV 0.01f

#define OFF_MIX   (NG * DD)
#define OFF_SCALE (OFF_MIX + NG * KK)
#define OFF_ALPHA (OFF_SCALE + NG)
#define OFF_BETA  (OFF_ALPHA + NG)

// ---- packed f32x2 helpers (sm_103a) ----------------------------------------
__device__ __forceinline__ double add2(double a, double b) {
    double r; asm("add.rn.f32x2 %0,%1,%2;" : "=d"(r) : "d"(a), "d"(b)); return r;
}
__device__ __forceinline__ double fma2(double a, double b, double c) {
    double r; asm("fma.rn.f32x2 %0,%1,%2,%3;" : "=d"(r) : "d"(a), "d"(b), "d"(c)); return r;
}
__device__ __forceinline__ double pack2(float lo, float hi) {
    double r; asm("mov.b64 %0,{%1,%2};" : "=d"(r) : "f"(lo), "f"(hi)); return r;
}
__device__ __forceinline__ float2 unpack2(double v) {
    float2 r; asm("mov.b64 {%0,%1},%2;" : "=f"(r.x), "=f"(r.y) : "d"(v)); return r;
}
__device__ __forceinline__ float softplus_f(float v) {
    return v > 20.0f ? v : log1pf(expf(v));
}

// ============================================================================
// Kernel A: per-group statistics. Pure streaming, double-buffered, no tail.
// Writes rep into out[g*DD .. ]. One warp per group, 8 groups per block.
// ============================================================================
__global__ __launch_bounds__(256, 4)
void stats_kernel(
    const float* __restrict__ x,
    const float* __restrict__ y,
    const float* __restrict__ anchor_x,
    const float* __restrict__ anchor_y,
    float* __restrict__ out)
{
    const int tid = threadIdx.x;
    const int w   = tid >> 5;
    const int l   = tid & 31;
    const int g   = blockIdx.x * GPB + w;

    const float4* xg = reinterpret_cast<const float4*>(x + (size_t)g * SS * DD) + l;
    const float*  yg = y + (size_t)g * SS;
    float4 a4 = reinterpret_cast<const float4*>(anchor_x + (size_t)g * DD)[l];
    const float ayv = anchor_y[g];

    const double na_lo = pack2(-a4.x, -a4.y);
    const double na_hi = pack2(-a4.z, -a4.w);

    double sx_lo = 0.0, sx_hi = 0.0;
    double sxy_lo = 0.0, sxy_hi = 0.0;
    double sxx2 = 0.0;
    float  sy = 0.f;

    // double-buffered pipeline: batches of 4 rows
    float4 c0, c1, c2, c3;
    float  yv0, yv1, yv2, yv3;
    c0 = xg[0 * (DD / 4)]; c1 = xg[1 * (DD / 4)];
    c2 = xg[2 * (DD / 4)]; c3 = xg[3 * (DD / 4)];
    yv0 = yg[0]; yv1 = yg[1]; yv2 = yg[2]; yv3 = yg[3];

    #pragma unroll
    for (int b = 0; b < SS / 4; ++b) {
        float4 n0, n1, n2, n3;
        float  yn0, yn1, yn2, yn3;
        if (b < SS / 4 - 1) {
            const int base = (b + 1) * 4;
            n0 = xg[(base + 0) * (DD / 4)];
            n1 = xg[(base + 1) * (DD / 4)];
            n2 = xg[(base + 2) * (DD / 4)];
            n3 = xg[(base + 3) * (DD / 4)];
            yn0 = yg[base + 0]; yn1 = yg[base + 1];
            yn2 = yg[base + 2]; yn3 = yg[base + 3];
        }
        // compute current batch while next batch loads are in flight
        {
            float4 cc[4] = {c0, c1, c2, c3};
            float  yy[4] = {yv0, yv1, yv2, yv3};
            #pragma unroll
            for (int k = 0; k < 4; ++k) {
                double2 xd = *reinterpret_cast<double2*>(&cc[k]);
                float yr = yy[k] - ayv;
                double yr2 = pack2(yr, yr);
                double xr_lo = add2(xd.x, na_lo);
                double xr_hi = add2(xd.y, na_hi);
                sx_lo  = add2(sx_lo, xr_lo);
                sx_hi  = add2(sx_hi, xr_hi);
                sxy_lo = fma2(xr_lo, yr2, sxy_lo);
                sxy_hi = fma2(xr_hi, yr2, sxy_hi);
                sxx2   = fma2(xr_lo, xr_lo, sxx2);
                sxx2   = fma2(xr_hi, xr_hi, sxx2);
                sy += yr;
            }
        }
        c0 = n0; c1 = n1; c2 = n2; c3 = n3;
        yv0 = yn0; yv1 = yn1; yv2 = yn2; yv3 = yn3;
    }

    float2 sxxp = unpack2(sxx2);
    float sxx = sxxp.x + sxxp.y;
    float2 sxl = unpack2(sx_lo),  sxh = unpack2(sx_hi);
    float2 syl = unpack2(sxy_lo), syh = unpack2(sxy_hi);
    float tot = sxl.x + sxl.y + sxh.x + sxh.y;

    #pragma unroll
    for (int o = 16; o > 0; o >>= 1) {
        sxx += __shfl_xor_sync(0xFFFFFFFFu, sxx, o);
        tot += __shfl_xor_sync(0xFFFFFFFFu, tot, o);
    }

    const float nD      = (float)(SS * DD);
    const float var     = (sxx - tot * tot / nD) / (nD - 1.0f);
    const float inv_var = 1.0f / var;
    const float c       = sy / (float)SS;
    const float inv_nm1 = 1.0f / (float)(SS - 1);

    float4 rep;
    rep.x = (syl.x - sxl.x * c) * inv_nm1 * inv_var;
    rep.y = (syl.y - sxl.y * c) * inv_nm1 * inv_var;
    rep.z = (syh.x - sxh.x * c) * inv_nm1 * inv_var;
    rep.w = (syh.y - sxh.y * c) * inv_nm1 * inv_var;

    reinterpret_cast<float4*>(out + (size_t)g * DD)[l] = rep;
}

// ============================================================================
// Kernel B: MLP head. Reads rep from out (L2-hot), 8 groups per block.
// Phase 2b/2c are warp-per-group with shuffle reductions (no serial tail).
// ============================================================================
__global__ __launch_bounds__(256)
void mlp_kernel(
    const float* __restrict__ W1,
    const float* __restrict__ b1,
    const float* __restrict__ W2,
    const float* __restrict__ b2,
    float* __restrict__ out)
{
    __shared__ float rep_s[GPB][DD];
    __shared__ float h_s[GPB][HH + 1];

    const int tid = threadIdx.x;

    // stage rep: 256 threads x 1 float4 = 1024 floats, fully coalesced
    {
        const float4* repg =
            reinterpret_cast<const float4*>(out + (size_t)blockIdx.x * GPB * DD);
        reinterpret_cast<float4*>(&rep_s[0][0])[tid] = repg[tid];
    }
    __syncthreads();

    // h = tanh(rep @ W1 + b1), thread = hidden unit j, 8 groups per thread
    {
        const int j = tid;
        float acc[GPB];
        const float bj = b1[j];
        #pragma unroll
        for (int gg = 0; gg < GPB; ++gg) acc[gg] = bj;

        #pragma unroll 4
        for (int d = 0; d < DD; d += 4) {
            float w0  = W1[(d + 0) * HH + j];
            float w1v = W1[(d + 1) * HH + j];
            float w2v = W1[(d + 2) * HH + j];
            float w3v = W1[(d + 3) * HH + j];
            #pragma unroll
            for (int gg = 0; gg < GPB; ++gg) {
                float4 r = *reinterpret_cast<const float4*>(&rep_s[gg][d]);
                acc[gg] = fmaf(r.x, w0,  acc[gg]);
                acc[gg] = fmaf(r.y, w1v, acc[gg]);
                acc[gg] = fmaf(r.z, w2v, acc[gg]);
                acc[gg] = fmaf(r.w, w3v, acc[gg]);
            }
        }
        #pragma unroll
        for (int gg = 0; gg < GPB; ++gg) h_s[gg][j] = tanhf(acc[gg]);
    }
    __syncthreads();

    // out = h @ W2 + b2 : one warp per group, lanes parallel over hidden dim
    {
        const int w = tid >> 5;    // group
        const int l = tid & 31;
        const int gl = blockIdx.x * GPB + w;

        float acc[KK + 2];
        #pragma unroll
        for (int k = 0; k < KK + 2; ++k) acc[k] = 0.f;

        #pragma unroll
        for (int t = 0; t < HH / 32; ++t) {
            const int j = l + 32 * t;
            const float hv = h_s[w][j];
            #pragma unroll
            for (int k = 0; k < KK + 2; ++k)
                acc[k] = fmaf(hv, W2[j * (KK + 2) + k], acc[k]);
        }
        #pragma unroll
        for (int k = 0; k < KK + 2; ++k) {
            #pragma unroll
            for (int o = 16; o > 0; o >>= 1)
                acc[k] += __shfl_xor_sync(0xFFFFFFFFu, acc[k], o);
        }

        if (l == 0) {
            float o0 = acc[0] + b2[0];
            float o1 = acc[1] + b2[1];
            float alpha = softplus_f(o0) * (1.0f - EPSV) + EPSV;
            float beta  = softplus_f(o1) * (1.0f - EPSV) + EPSV;

            float ok[KK];
            float m = -INFINITY;
            #pragma unroll
            for (int k = 0; k < KK; ++k) {
                ok[k] = acc[2 + k] + b2[2 + k];
                m = fmaxf(m, ok[k]);
            }
            float s = 0.f;
            #pragma unroll
            for (int k = 0; k < KK; ++k) { ok[k] = expf(ok[k] - m); s += ok[k]; }
            float inv = 1.0f / s;
            #pragma unroll
            for (int k = 0; k < KK; ++k)
                out[OFF_MIX + (size_t)gl * KK + k] = ok[k] * inv;

            out[OFF_SCALE + gl] = sqrtf(beta / alpha);
            out[OFF_ALPHA + gl] = alpha;
            out[OFF_BETA  + gl] = beta;
        }
    }
}

extern "C" void kernel_launch(void* const* d_in, const int* in_sizes, int n_in,
                              void* d_out, int out_size) {
    // inputs (metadata order): index, x, y, anchor_x, anchor_y, W1, b1, W2, b2
    const float* x        = (const float*)d_in[1];
    const float* y        = (const float*)d_in[2];
    const float* anchor_x = (const float*)d_in[3];
    const float* anchor_y = (const float*)d_in[4];
    const float* W1       = (const float*)d_in[5];
    const float* b1       = (const float*)d_in[6];
    const float* W2       = (const float*)d_in[7];
    const float* b2       = (const float*)d_in[8];
    float* out            = (float*)d_out;

    stats_kernel<<<NG / GPB, 256>>>(x, y, anchor_x, anchor_y, out);
    mlp_kernel<<<NG / GPB, 256>>>(W1, b1, W2, b2, out);
}

// round 5
// speedup vs baseline: 1.4258x; 1.4258x over previous
#include <cuda_runtime.h>
#include <math.h>

#define NG   8192
#define SS   64
#define DD   128
#define HH   256
#define KK   8
#define GPB  8
#define EPSV 0.01f

#define OFF_MIX   (NG * DD)
#define OFF_SCALE (OFF_MIX + NG * KK)
#define OFF_ALPHA (OFF_SCALE + NG)
#define OFF_BETA  (OFF_ALPHA + NG)

// ---- packed f32x2 helpers (sm_103a) ----------------------------------------
__device__ __forceinline__ double add2(double a, double b) {
    double r; asm("add.rn.f32x2 %0,%1,%2;" : "=d"(r) : "d"(a), "d"(b)); return r;
}
__device__ __forceinline__ double fma2(double a, double b, double c) {
    double r; asm("fma.rn.f32x2 %0,%1,%2,%3;" : "=d"(r) : "d"(a), "d"(b), "d"(c)); return r;
}
__device__ __forceinline__ double pack2(float lo, float hi) {
    double r; asm("mov.b64 %0,{%1,%2};" : "=d"(r) : "f"(lo), "f"(hi)); return r;
}
__device__ __forceinline__ float2 unpack2(double v) {
    float2 r; asm("mov.b64 {%0,%1},%2;" : "=f"(r.x), "=f"(r.y) : "d"(v)); return r;
}
__device__ __forceinline__ float softplus_f(float v) {
    return v > 20.0f ? v : log1pf(expf(v));
}

// ============================================================================
// Kernel A: per-group statistics (UNCHANGED from R4: ~46us @ 73% DRAM).
// ============================================================================
__global__ __launch_bounds__(256, 4)
void stats_kernel(
    const float* __restrict__ x,
    const float* __restrict__ y,
    const float* __restrict__ anchor_x,
    const float* __restrict__ anchor_y,
    float* __restrict__ out)
{
    const int tid = threadIdx.x;
    const int w   = tid >> 5;
    const int l   = tid & 31;
    const int g   = blockIdx.x * GPB + w;

    const float4* xg = reinterpret_cast<const float4*>(x + (size_t)g * SS * DD) + l;
    const float*  yg = y + (size_t)g * SS;
    float4 a4 = reinterpret_cast<const float4*>(anchor_x + (size_t)g * DD)[l];
    const float ayv = anchor_y[g];

    const double na_lo = pack2(-a4.x, -a4.y);
    const double na_hi = pack2(-a4.z, -a4.w);

    double sx_lo = 0.0, sx_hi = 0.0;
    double sxy_lo = 0.0, sxy_hi = 0.0;
    double sxx2 = 0.0;
    float  sy = 0.f;

    float4 c0, c1, c2, c3;
    float  yv0, yv1, yv2, yv3;
    c0 = xg[0 * (DD / 4)]; c1 = xg[1 * (DD / 4)];
    c2 = xg[2 * (DD / 4)]; c3 = xg[3 * (DD / 4)];
    yv0 = yg[0]; yv1 = yg[1]; yv2 = yg[2]; yv3 = yg[3];

    #pragma unroll
    for (int b = 0; b < SS / 4; ++b) {
        float4 n0, n1, n2, n3;
        float  yn0, yn1, yn2, yn3;
        if (b < SS / 4 - 1) {
            const int base = (b + 1) * 4;
            n0 = xg[(base + 0) * (DD / 4)];
            n1 = xg[(base + 1) * (DD / 4)];
            n2 = xg[(base + 2) * (DD / 4)];
            n3 = xg[(base + 3) * (DD / 4)];
            yn0 = yg[base + 0]; yn1 = yg[base + 1];
            yn2 = yg[base + 2]; yn3 = yg[base + 3];
        }
        {
            float4 cc[4] = {c0, c1, c2, c3};
            float  yy[4] = {yv0, yv1, yv2, yv3};
            #pragma unroll
            for (int k = 0; k < 4; ++k) {
                double2 xd = *reinterpret_cast<double2*>(&cc[k]);
                float yr = yy[k] - ayv;
                double yr2 = pack2(yr, yr);
                double xr_lo = add2(xd.x, na_lo);
                double xr_hi = add2(xd.y, na_hi);
                sx_lo  = add2(sx_lo, xr_lo);
                sx_hi  = add2(sx_hi, xr_hi);
                sxy_lo = fma2(xr_lo, yr2, sxy_lo);
                sxy_hi = fma2(xr_hi, yr2, sxy_hi);
                sxx2   = fma2(xr_lo, xr_lo, sxx2);
                sxx2   = fma2(xr_hi, xr_hi, sxx2);
                sy += yr;
            }
        }
        c0 = n0; c1 = n1; c2 = n2; c3 = n3;
        yv0 = yn0; yv1 = yn1; yv2 = yn2; yv3 = yn3;
    }

    float2 sxxp = unpack2(sxx2);
    float sxx = sxxp.x + sxxp.y;
    float2 sxl = unpack2(sx_lo),  sxh = unpack2(sx_hi);
    float2 syl = unpack2(sxy_lo), syh = unpack2(sxy_hi);
    float tot = sxl.x + sxl.y + sxh.x + sxh.y;

    #pragma unroll
    for (int o = 16; o > 0; o >>= 1) {
        sxx += __shfl_xor_sync(0xFFFFFFFFu, sxx, o);
        tot += __shfl_xor_sync(0xFFFFFFFFu, tot, o);
    }

    const float nD      = (float)(SS * DD);
    const float var     = (sxx - tot * tot / nD) / (nD - 1.0f);
    const float inv_var = 1.0f / var;
    const float c       = sy / (float)SS;
    const float inv_nm1 = 1.0f / (float)(SS - 1);

    float4 rep;
    rep.x = (syl.x - sxl.x * c) * inv_nm1 * inv_var;
    rep.y = (syl.y - sxl.y * c) * inv_nm1 * inv_var;
    rep.z = (syh.x - sxh.x * c) * inv_nm1 * inv_var;
    rep.w = (syh.y - sxh.y * c) * inv_nm1 * inv_var;

    reinterpret_cast<float4*>(out + (size_t)g * DD)[l] = rep;
}

// ============================================================================
// Kernel B: MLP head, rebuilt for L1-wavefront / FMA-issue economy.
//   - 128 threads/block; each thread owns hidden units (tid, tid+128).
//   - rep stored group-pair-interleaved; one LDS.128 feeds 2 dims x 2 groups
//     and is reused by both hidden units -> 8 MACs per LDS.128.
//   - fma.rn.f32x2 over group pairs: 1024 fma2 per thread for 2048 MACs.
//   - W2 transposed into smem -> stride-1 conflict-free phase 2b.
// ============================================================================
__global__ __launch_bounds__(128)
void mlp_kernel(
    const float* __restrict__ W1,
    const float* __restrict__ b1,
    const float* __restrict__ W2,
    const float* __restrict__ b2,
    float* __restrict__ out)
{
    __shared__ double2 rep_p[4][DD / 2];      // [group pair][dim pair] 4 KB
    __shared__ float   h_s[GPB][HH + 1];      // 8.2 KB
    __shared__ float   w2t[KK + 2][HH];       // 10 KB, transposed W2

    const int tid = threadIdx.x;              // 0..127

    // ---- stage rep (pair-interleaved) + transposed W2 ------------------------
    {
        const float4* repg =
            reinterpret_cast<const float4*>(out + (size_t)blockIdx.x * GPB * DD);
        #pragma unroll
        for (int i = tid; i < 256; i += 128) {
            float4 v = repg[i];
            int gg  = i >> 5;
            int d0  = 4 * (i & 31);
            int p   = gg >> 1;
            int sel = gg & 1;
            float* base = reinterpret_cast<float*>(&rep_p[p][0]);
            base[2 * (d0 + 0) + sel] = v.x;
            base[2 * (d0 + 1) + sel] = v.y;
            base[2 * (d0 + 2) + sel] = v.z;
            base[2 * (d0 + 3) + sel] = v.w;
        }
        #pragma unroll
        for (int i = tid; i < HH * (KK + 2); i += 128) {
            int j = i / (KK + 2);
            int k = i - j * (KK + 2);
            w2t[k][j] = W2[i];
        }
    }
    __syncthreads();

    // ---- layer 1: h = tanh(rep @ W1 + b1) ------------------------------------
    {
        const int j0 = tid;
        const int j1 = tid + 128;
        const float b0 = b1[j0], b1v = b1[j1];

        double acc[4][2];
        #pragma unroll
        for (int p = 0; p < 4; ++p) {
            acc[p][0] = pack2(b0, b0);
            acc[p][1] = pack2(b1v, b1v);
        }

        #pragma unroll 4
        for (int d = 0; d < DD; d += 2) {
            float w00 = W1[(d + 0) * HH + j0];
            float w01 = W1[(d + 0) * HH + j1];
            float w10 = W1[(d + 1) * HH + j0];
            float w11 = W1[(d + 1) * HH + j1];
            double wd00 = pack2(w00, w00);
            double wd01 = pack2(w01, w01);
            double wd10 = pack2(w10, w10);
            double wd11 = pack2(w11, w11);
            #pragma unroll
            for (int p = 0; p < 4; ++p) {
                double2 rp = rep_p[p][d >> 1];   // broadcast LDS.128
                acc[p][0] = fma2(rp.x, wd00, acc[p][0]);
                acc[p][0] = fma2(rp.y, wd10, acc[p][0]);
                acc[p][1] = fma2(rp.x, wd01, acc[p][1]);
                acc[p][1] = fma2(rp.y, wd11, acc[p][1]);
            }
        }

        #pragma unroll
        for (int p = 0; p < 4; ++p) {
            float2 h0 = unpack2(acc[p][0]);
            float2 h1 = unpack2(acc[p][1]);
            h_s[2 * p + 0][j0] = tanhf(h0.x);
            h_s[2 * p + 1][j0] = tanhf(h0.y);
            h_s[2 * p + 0][j1] = tanhf(h1.x);
            h_s[2 * p + 1][j1] = tanhf(h1.y);
        }
    }
    __syncthreads();

    // ---- layer 2 + heads: warp handles 2 groups ------------------------------
    {
        const int w = tid >> 5;               // 0..3 -> groups 2w, 2w+1
        const int l = tid & 31;

        float acc[2][KK + 2];
        #pragma unroll
        for (int gi = 0; gi < 2; ++gi)
            #pragma unroll
            for (int k = 0; k < KK + 2; ++k) acc[gi][k] = 0.f;

        #pragma unroll
        for (int t = 0; t < HH / 32; ++t) {
            const int j = 32 * t + l;
            const float h0 = h_s[2 * w + 0][j];
            const float h1 = h_s[2 * w + 1][j];
            #pragma unroll
            for (int k = 0; k < KK + 2; ++k) {
                const float wv = w2t[k][j];
                acc[0][k] = fmaf(h0, wv, acc[0][k]);
                acc[1][k] = fmaf(h1, wv, acc[1][k]);
            }
        }
        #pragma unroll
        for (int gi = 0; gi < 2; ++gi)
            #pragma unroll
            for (int k = 0; k < KK + 2; ++k)
                #pragma unroll
                for (int o = 16; o > 0; o >>= 1)
                    acc[gi][k] += __shfl_xor_sync(0xFFFFFFFFu, acc[gi][k], o);

        if (l == 0) {
            #pragma unroll
            for (int gi = 0; gi < 2; ++gi) {
                const int gl = blockIdx.x * GPB + 2 * w + gi;
                float o0 = acc[gi][0] + b2[0];
                float o1 = acc[gi][1] + b2[1];
                float alpha = softplus_f(o0) * (1.0f - EPSV) + EPSV;
                float beta  = softplus_f(o1) * (1.0f - EPSV) + EPSV;

                float ok[KK];
                float m = -INFINITY;
                #pragma unroll
                for (int k = 0; k < KK; ++k) {
                    ok[k] = acc[gi][2 + k] + b2[2 + k];
                    m = fmaxf(m, ok[k]);
                }
                float s = 0.f;
                #pragma unroll
                for (int k = 0; k < KK; ++k) { ok[k] = expf(ok[k] - m); s += ok[k]; }
                float inv = 1.0f / s;
                #pragma unroll
                for (int k = 0; k < KK; ++k)
                    out[OFF_MIX + (size_t)gl * KK + k] = ok[k] * inv;

                out[OFF_SCALE + gl] = sqrtf(beta / alpha);
                out[OFF_ALPHA + gl] = alpha;
                out[OFF_BETA  + gl] = beta;
            }
        }
    }
}

extern "C" void kernel_launch(void* const* d_in, const int* in_sizes, int n_in,
                              void* d_out, int out_size) {
    // inputs (metadata order): index, x, y, anchor_x, anchor_y, W1, b1, W2, b2
    const float* x        = (const float*)d_in[1];
    const float* y        = (const float*)d_in[2];
    const float* anchor_x = (const float*)d_in[3];
    const float* anchor_y = (const float*)d_in[4];
    const float* W1       = (const float*)d_in[5];
    const float* b1       = (const float*)d_in[6];
    const float* W2       = (const float*)d_in[7];
    const float* b2       = (const float*)d_in[8];
    float* out            = (float*)d_out;

    stats_kernel<<<NG / GPB, 256>>>(x, y, anchor_x, anchor_y, out);
    mlp_kernel<<<NG / GPB, 128>>>(W1, b1, W2, b2, out);
}